// round 1
// baseline (speedup 1.0000x reference)
#include <cuda_runtime.h>
#include <cstdint>

// Problem constants
#define BB   4
#define SS   2048
#define DD   1024
#define HH   16
#define HD   64
#define BS   (BB*SS)        // 8192

// Scratch (device globals — no allocation allowed)
__device__ float g_proj[(size_t)BS * 3 * DD];   // [8192, 3072]  k|q|v
__device__ float g_attn[(size_t)BS * DD];       // [8192, 1024]

// ---------------------------------------------------------------------------
// Generic tiled SGEMM with bias: C[M,N] = A[M,K] @ B[K,N] + bias[N]
// 128x128 tile, K-step 8, 256 threads, 8x8 micro-tile per thread.
// All dims divisible by tile sizes for this problem.
// ---------------------------------------------------------------------------
__global__ __launch_bounds__(256) void sgemm_bias(
    const float* __restrict__ A, const float* __restrict__ B,
    const float* __restrict__ bias, float* __restrict__ C,
    int M, int N, int K)
{
    __shared__ float As[8][128];
    __shared__ float Bs[8][128];

    const int tid = threadIdx.x;
    const int row0 = blockIdx.y * 128;
    const int col0 = blockIdx.x * 128;
    const int tx = tid & 15;       // 0..15 -> 8 cols each
    const int ty = tid >> 4;       // 0..15 -> 8 rows each

    // load mapping
    const int am = tid >> 1;            // 0..127
    const int ak = (tid & 1) * 4;       // 0 or 4
    const int bk = tid >> 5;            // 0..7
    const int bn = (tid & 31) * 4;      // 0..124

    float acc[8][8];
#pragma unroll
    for (int i = 0; i < 8; i++)
#pragma unroll
        for (int j = 0; j < 8; j++) acc[i][j] = 0.f;

    for (int k0 = 0; k0 < K; k0 += 8) {
        float4 av = *(const float4*)(A + (size_t)(row0 + am) * K + k0 + ak);
        float4 bv = *(const float4*)(B + (size_t)(k0 + bk) * N + col0 + bn);
        __syncthreads();
        As[ak + 0][am] = av.x;
        As[ak + 1][am] = av.y;
        As[ak + 2][am] = av.z;
        As[ak + 3][am] = av.w;
        *(float4*)(&Bs[bk][bn]) = bv;
        __syncthreads();

#pragma unroll
        for (int kk = 0; kk < 8; kk++) {
            float4 a0 = *(float4*)(&As[kk][ty * 8]);
            float4 a1 = *(float4*)(&As[kk][ty * 8 + 4]);
            float4 b0 = *(float4*)(&Bs[kk][tx * 8]);
            float4 b1 = *(float4*)(&Bs[kk][tx * 8 + 4]);
            float a[8] = {a0.x, a0.y, a0.z, a0.w, a1.x, a1.y, a1.z, a1.w};
            float b[8] = {b0.x, b0.y, b0.z, b0.w, b1.x, b1.y, b1.z, b1.w};
#pragma unroll
            for (int i = 0; i < 8; i++)
#pragma unroll
                for (int j = 0; j < 8; j++) acc[i][j] += a[i] * b[j];
        }
    }

#pragma unroll
    for (int i = 0; i < 8; i++) {
        const int r = row0 + ty * 8 + i;
#pragma unroll
        for (int j = 0; j < 8; j += 4) {
            const int c = col0 + tx * 8 + j;
            float4 o;
            o.x = acc[i][j + 0] + bias[c + 0];
            o.y = acc[i][j + 1] + bias[c + 1];
            o.z = acc[i][j + 2] + bias[c + 2];
            o.w = acc[i][j + 3] + bias[c + 3];
            *(float4*)(C + (size_t)r * N + c) = o;
        }
    }
}

// ---------------------------------------------------------------------------
// Flash-attention (fp32, causal). One CTA per (q-block of 64 rows, b*H+h).
// 256 threads. O accumulator 4x4 per thread in registers.
// proj layout: [BS, 3*DD], columns [0:D)=k, [D:2D)=q, [2D:3D)=v.
// out: [BS, DD], head h at column h*HD.
// ---------------------------------------------------------------------------
#define LDP 68   // smem row pitch (floats)

__global__ __launch_bounds__(256) void attn_kernel(
    const float* __restrict__ proj, float* __restrict__ out)
{
    extern __shared__ float sm[];
    float* Qs = sm;                 // 64*LDP
    float* Ks = Qs + 64 * LDP;
    float* Vs = Ks + 64 * LDP;
    float* Ps = Vs + 64 * LDP;      // scores / probabilities
    float* mrow = Ps + 64 * LDP;    // 64
    float* lrow = mrow + 64;        // 64
    float* arow = lrow + 64;        // 64

    const int qb = blockIdx.x;          // 0..S/64-1
    const int bh = blockIdx.y;          // 0..B*H-1
    const int b = bh / HH, h = bh % HH;
    const int tid = threadIdx.x;
    const int tx = tid & 15;            // 4 cols each
    const int ty = tid >> 4;            // 4 rows each

    const size_t rowstride = 3 * DD;
    const float* base = proj + (size_t)b * SS * rowstride;
    const int koff = h * HD;
    const int qoff = DD + h * HD;
    const int voff = 2 * DD + h * HD;

    // Load Q tile (64 rows x 64 cols)
    for (int i = tid; i < 64 * 16; i += 256) {
        int r = i >> 4, c4 = (i & 15) * 4;
        *(float4*)(Qs + r * LDP + c4) =
            *(const float4*)(base + (size_t)(qb * 64 + r) * rowstride + qoff + c4);
    }
    if (tid < 64) { mrow[tid] = -1e30f; lrow[tid] = 0.f; }

    float o[4][4];
#pragma unroll
    for (int i = 0; i < 4; i++)
#pragma unroll
        for (int j = 0; j < 4; j++) o[i][j] = 0.f;

    const float scale = 0.125f;   // 1/sqrt(64)

    for (int kb = 0; kb <= qb; ++kb) {
        __syncthreads();   // previous iteration's P@V done before reloading K/V
        for (int i = tid; i < 64 * 16; i += 256) {
            int r = i >> 4, c4 = (i & 15) * 4;
            const float* rp = base + (size_t)(kb * 64 + r) * rowstride;
            *(float4*)(Ks + r * LDP + c4) = *(const float4*)(rp + koff + c4);
            *(float4*)(Vs + r * LDP + c4) = *(const float4*)(rp + voff + c4);
        }
        __syncthreads();

        // scores: sacc[i][j] = Q[ty*4+i] . K[tx*4+j]
        float sacc[4][4];
#pragma unroll
        for (int i = 0; i < 4; i++)
#pragma unroll
            for (int j = 0; j < 4; j++) sacc[i][j] = 0.f;

#pragma unroll 4
        for (int d = 0; d < 64; d += 4) {
            float4 qv[4], kv[4];
#pragma unroll
            for (int i = 0; i < 4; i++) qv[i] = *(float4*)(Qs + (ty * 4 + i) * LDP + d);
#pragma unroll
            for (int j = 0; j < 4; j++) kv[j] = *(float4*)(Ks + (tx * 4 + j) * LDP + d);
#pragma unroll
            for (int i = 0; i < 4; i++)
#pragma unroll
                for (int j = 0; j < 4; j++) {
                    sacc[i][j] += qv[i].x * kv[j].x;
                    sacc[i][j] += qv[i].y * kv[j].y;
                    sacc[i][j] += qv[i].z * kv[j].z;
                    sacc[i][j] += qv[i].w * kv[j].w;
                }
        }

        // masked, scaled scores -> Ps
        const int qg0 = qb * 64, kg0 = kb * 64;
#pragma unroll
        for (int i = 0; i < 4; i++) {
            int qi = qg0 + ty * 4 + i;
#pragma unroll
            for (int j = 0; j < 4; j++) {
                int kj = kg0 + tx * 4 + j;
                Ps[(ty * 4 + i) * LDP + tx * 4 + j] =
                    (kj <= qi) ? sacc[i][j] * scale : -1e30f;
            }
        }
        __syncthreads();

        // online softmax row update (one thread per row)
        if (tid < 64) {
            const int r = tid;
            float* srow = Ps + r * LDP;
            float mold = mrow[r];
            float mx = mold;
#pragma unroll 8
            for (int j = 0; j < 64; j++) mx = fmaxf(mx, srow[j]);
            float alpha = __expf(mold - mx);
            float sum = 0.f;
#pragma unroll 8
            for (int j = 0; j < 64; j++) {
                float p = __expf(srow[j] - mx);
                srow[j] = p;
                sum += p;
            }
            lrow[r] = lrow[r] * alpha + sum;
            arow[r] = alpha;
            mrow[r] = mx;
        }
        __syncthreads();

        // rescale O, then O += P @ V
#pragma unroll
        for (int i = 0; i < 4; i++) {
            float a = arow[ty * 4 + i];
#pragma unroll
            for (int j = 0; j < 4; j++) o[i][j] *= a;
        }

#pragma unroll 4
        for (int j4 = 0; j4 < 64; j4 += 4) {
            float4 pv[4], vv[4];
#pragma unroll
            for (int i = 0; i < 4; i++) pv[i] = *(float4*)(Ps + (ty * 4 + i) * LDP + j4);
#pragma unroll
            for (int jj = 0; jj < 4; jj++) vv[jj] = *(float4*)(Vs + (j4 + jj) * LDP + tx * 4);
#pragma unroll
            for (int i = 0; i < 4; i++) {
                float p0 = pv[i].x, p1 = pv[i].y, p2 = pv[i].z, p3 = pv[i].w;
                o[i][0] += p0 * vv[0].x + p1 * vv[1].x + p2 * vv[2].x + p3 * vv[3].x;
                o[i][1] += p0 * vv[0].y + p1 * vv[1].y + p2 * vv[2].y + p3 * vv[3].y;
                o[i][2] += p0 * vv[0].z + p1 * vv[1].z + p2 * vv[2].z + p3 * vv[3].z;
                o[i][3] += p0 * vv[0].w + p1 * vv[1].w + p2 * vv[2].w + p3 * vv[3].w;
            }
        }
    }

    // write normalized output
#pragma unroll
    for (int i = 0; i < 4; i++) {
        float inv = 1.f / lrow[ty * 4 + i];
        float4 ov;
        ov.x = o[i][0] * inv;
        ov.y = o[i][1] * inv;
        ov.z = o[i][2] * inv;
        ov.w = o[i][3] * inv;
        *(float4*)(out + (size_t)(b * SS + qb * 64 + ty * 4 + i) * DD + h * HD + tx * 4) = ov;
    }
}

// ---------------------------------------------------------------------------
extern "C" void kernel_launch(void* const* d_in, const int* in_sizes, int n_in,
                              void* d_out, int out_size)
{
    const float* x     = (const float*)d_in[0];
    const float* W_in  = (const float*)d_in[1];
    const float* b_in  = (const float*)d_in[2];
    const float* W_out = (const float*)d_in[3];
    const float* b_out = (const float*)d_in[4];
    float* out = (float*)d_out;

    float* proj = nullptr;
    float* attn = nullptr;
    cudaGetSymbolAddress((void**)&proj, g_proj);
    cudaGetSymbolAddress((void**)&attn, g_attn);

    // 1) QKV projection: [8192,1024] @ [1024,3072] + b_in
    {
        dim3 grid(3 * DD / 128, BS / 128);
        sgemm_bias<<<grid, 256>>>(x, W_in, b_in, proj, BS, 3 * DD, DD);
    }

    // 2) attention
    {
        const int smem_bytes = (4 * 64 * LDP + 3 * 64) * (int)sizeof(float); // 70400
        cudaFuncSetAttribute(attn_kernel, cudaFuncAttributeMaxDynamicSharedMemorySize, smem_bytes);
        dim3 grid(SS / 64, BB * HH);
        attn_kernel<<<grid, 256, smem_bytes>>>(proj, attn);
    }

    // 3) output projection: [8192,1024] @ [1024,1024] + b_out
    {
        dim3 grid(DD / 128, BS / 128);
        sgemm_bias<<<grid, 256>>>(attn, W_out, b_out, out, BS, DD, DD);
    }
}

// round 3
// speedup vs baseline: 1.2649x; 1.2649x over previous
#include <cuda_runtime.h>
#include <cuda_bf16.h>
#include <cstdint>

// Problem constants
#define BB   4
#define SS   2048
#define DD   1024
#define HH   16
#define HD   64
#define BS   (BB*SS)        // 8192

__device__ __forceinline__ uint32_t smem_u32(const void* p) {
    uint32_t a;
    asm("{ .reg .u64 t; cvta.to.shared.u64 t, %1; cvt.u32.u64 %0, t; }" : "=r"(a) : "l"(p));
    return a;
}

// ---------------------------------------------------------------------------
// Scratch (device globals)
// ---------------------------------------------------------------------------
__device__ float g_proj[(size_t)BS * 3 * DD];     // [8192, 3072]  k|q|v
__device__ float g_attn[(size_t)BS * DD];         // [8192, 1024]
__device__ __nv_bfloat16 g_xh[(size_t)BS * DD];
__device__ __nv_bfloat16 g_xl[(size_t)BS * DD];
__device__ __nv_bfloat16 g_w1h[(size_t)(3*DD) * DD]; // W_in^T  [3072,1024]
__device__ __nv_bfloat16 g_w1l[(size_t)(3*DD) * DD];
__device__ __nv_bfloat16 g_w2h[(size_t)DD * DD];     // W_out^T [1024,1024]
__device__ __nv_bfloat16 g_w2l[(size_t)DD * DD];
__device__ __nv_bfloat16 g_ah[(size_t)BS * DD];
__device__ __nv_bfloat16 g_al[(size_t)BS * DD];

// ---------------------------------------------------------------------------
// Prep: elementwise bf16 2-term split   hi = bf16(v), lo = bf16(v - hi)
// ---------------------------------------------------------------------------
__global__ __launch_bounds__(256) void split_bf16(
    const float* __restrict__ src, __nv_bfloat16* __restrict__ hi,
    __nv_bfloat16* __restrict__ lo, int n4)
{
    int i = blockIdx.x * 256 + threadIdx.x;
    if (i >= n4) return;
    float4 v = ((const float4*)src)[i];
    __nv_bfloat162 h0, h1, l0, l1;
    float hx;
    hx = __bfloat162float(__float2bfloat16(v.x)); h0.x = __float2bfloat16(v.x); l0.x = __float2bfloat16(v.x - hx);
    hx = __bfloat162float(__float2bfloat16(v.y)); h0.y = __float2bfloat16(v.y); l0.y = __float2bfloat16(v.y - hx);
    hx = __bfloat162float(__float2bfloat16(v.z)); h1.x = __float2bfloat16(v.z); l1.x = __float2bfloat16(v.z - hx);
    hx = __bfloat162float(__float2bfloat16(v.w)); h1.y = __float2bfloat16(v.w); l1.y = __float2bfloat16(v.w - hx);
    ((__nv_bfloat162*)hi)[i*2+0] = h0; ((__nv_bfloat162*)hi)[i*2+1] = h1;
    ((__nv_bfloat162*)lo)[i*2+0] = l0; ((__nv_bfloat162*)lo)[i*2+1] = l1;
}

// ---------------------------------------------------------------------------
// Prep: transpose + split   W[K,N] -> Th/Tl[N,K]
// ---------------------------------------------------------------------------
__global__ __launch_bounds__(256) void transpose_split(
    const float* __restrict__ W, __nv_bfloat16* __restrict__ th,
    __nv_bfloat16* __restrict__ tl, int K, int N)
{
    __shared__ float tile[32][33];
    int k0 = blockIdx.y * 32, n0 = blockIdx.x * 32;
    int tx = threadIdx.x, ty = threadIdx.y;   // 32 x 8
#pragma unroll
    for (int j = 0; j < 32; j += 8)
        tile[ty + j][tx] = W[(size_t)(k0 + ty + j) * N + n0 + tx];
    __syncthreads();
#pragma unroll
    for (int j = 0; j < 32; j += 8) {
        float v = tile[tx][ty + j];
        __nv_bfloat16 h = __float2bfloat16(v);
        __nv_bfloat16 l = __float2bfloat16(v - __bfloat162float(h));
        size_t o = (size_t)(n0 + ty + j) * K + k0 + tx;
        th[o] = h; tl[o] = l;
    }
}

// ---------------------------------------------------------------------------
// mma.sync helpers (arch-generic tensor ISA, works at sm_103 baseline target)
// ---------------------------------------------------------------------------
__device__ __forceinline__ void ldsm_x4(uint32_t& r0, uint32_t& r1, uint32_t& r2, uint32_t& r3,
                                        uint32_t addr) {
    asm volatile("ldmatrix.sync.aligned.m8n8.x4.shared.b16 {%0,%1,%2,%3}, [%4];"
                 : "=r"(r0), "=r"(r1), "=r"(r2), "=r"(r3) : "r"(addr));
}
__device__ __forceinline__ void mma_bf16(float* d, const uint32_t* a, const uint32_t* b) {
    asm volatile(
        "mma.sync.aligned.m16n8k16.row.col.f32.bf16.bf16.f32 "
        "{%0,%1,%2,%3}, {%4,%5,%6,%7}, {%8,%9}, {%0,%1,%2,%3};"
        : "+f"(d[0]), "+f"(d[1]), "+f"(d[2]), "+f"(d[3])
        : "r"(a[0]), "r"(a[1]), "r"(a[2]), "r"(a[3]), "r"(b[0]), "r"(b[1]));
}

// ---------------------------------------------------------------------------
// GEMM on mma.sync, 3-term bf16 split, fp32 register accumulators.
// C[M,N] = A[M,K] @ B^T + bias, A,B stored split-bf16, B as [N,K] K-major.
// 128x128 tile, BK=32, 256 threads (8 warps, each 32m x 64n).
// ---------------------------------------------------------------------------
#define PA 40   // smem pitch in bf16 (conflict-free for ldmatrix, 16B-aligned)

__global__ __launch_bounds__(256) void gemm_mma(
    const __nv_bfloat16* __restrict__ Ah, const __nv_bfloat16* __restrict__ Al,
    const __nv_bfloat16* __restrict__ Bh, const __nv_bfloat16* __restrict__ Bl,
    const float* __restrict__ bias, float* __restrict__ C,
    int M, int N, int K)
{
    __shared__ __nv_bfloat16 sm[4 * 128 * PA];   // Ah | Al | Bh | Bl  (40960 B)
    __nv_bfloat16* sTile[4] = { sm, sm + 128*PA, sm + 2*128*PA, sm + 3*128*PA };

    const int tid  = threadIdx.x;
    const int wid  = tid >> 5;
    const int lane = tid & 31;
    const int wrow = wid & 3;        // m: 4 warps * 32
    const int wcol = wid >> 2;       // n: 2 warps * 64
    const int m0 = blockIdx.y * 128;
    const int n0 = blockIdx.x * 128;

    const uint32_t uS[4] = { smem_u32(sTile[0]), smem_u32(sTile[1]),
                             smem_u32(sTile[2]), smem_u32(sTile[3]) };

    // per-thread ldmatrix lane addressing components
    const int a_row = wrow * 32 + (lane & 7) + ((lane >> 3) & 1) * 8;
    const int a_k   = (lane >> 4) * 8;
    const int b_row = wcol * 64 + (lane >> 4) * 8 + (lane & 7);
    const int b_k   = ((lane >> 3) & 1) * 8;

    float acc[2][8][4];
#pragma unroll
    for (int i = 0; i < 2; i++)
#pragma unroll
        for (int j = 0; j < 8; j++)
#pragma unroll
            for (int v = 0; v < 4; v++) acc[i][j][v] = 0.f;

    const __nv_bfloat16* gsrc[4] = {
        Ah + (size_t)m0 * K, Al + (size_t)m0 * K,
        Bh + (size_t)n0 * K, Bl + (size_t)n0 * K };

    const int nchunks = K >> 5;
    for (int kc = 0; kc < nchunks; ++kc) {
        const int k0 = kc << 5;
        __syncthreads();
        // load 4 tiles of 128 rows x 32 bf16
#pragma unroll
        for (int v = tid; v < 2048; v += 256) {
            int t = v >> 9, idx = v & 511;
            int r = idx >> 2, c = idx & 3;
            uint4 d = *(const uint4*)(gsrc[t] + (size_t)r * K + k0 + c * 8);
            *(uint4*)(sTile[t] + r * PA + c * 8) = d;
        }
        __syncthreads();

#pragma unroll
        for (int pass = 0; pass < 3; pass++) {
            const uint32_t uA = (pass == 2) ? uS[1] : uS[0];
            const uint32_t uB = (pass == 1) ? uS[3] : uS[2];
#pragma unroll
            for (int ks = 0; ks < 2; ks++) {
                uint32_t afr[2][4];
#pragma unroll
                for (int mi = 0; mi < 2; mi++)
                    ldsm_x4(afr[mi][0], afr[mi][1], afr[mi][2], afr[mi][3],
                            uA + 2 * ((a_row + mi * 16) * PA + ks * 16 + a_k));
                uint32_t bfr[8][2];
#pragma unroll
                for (int j = 0; j < 4; j++) {
                    uint32_t r0, r1, r2, r3;
                    ldsm_x4(r0, r1, r2, r3,
                            uB + 2 * ((b_row + j * 16) * PA + ks * 16 + b_k));
                    bfr[2*j][0] = r0; bfr[2*j][1] = r1;
                    bfr[2*j+1][0] = r2; bfr[2*j+1][1] = r3;
                }
#pragma unroll
                for (int mi = 0; mi < 2; mi++)
#pragma unroll
                    for (int nj = 0; nj < 8; nj++)
                        mma_bf16(acc[mi][nj], afr[mi], bfr[nj]);
            }
        }
    }

    // epilogue: d0,d1 -> (row l/4, cols 2(l%4)..+1); d2,d3 -> row+8
    const int row0 = m0 + wrow * 32 + (lane >> 2);
    const int colb = n0 + wcol * 64 + (lane & 3) * 2;
#pragma unroll
    for (int mi = 0; mi < 2; mi++) {
#pragma unroll
        for (int nj = 0; nj < 8; nj++) {
            int c = colb + nj * 8;
            float2 bv = *(const float2*)(bias + c);
            float2 o0 = { acc[mi][nj][0] + bv.x, acc[mi][nj][1] + bv.y };
            float2 o1 = { acc[mi][nj][2] + bv.x, acc[mi][nj][3] + bv.y };
            *(float2*)(C + (size_t)(row0 + mi * 16) * N + c) = o0;
            *(float2*)(C + (size_t)(row0 + mi * 16 + 8) * N + c) = o1;
        }
    }
}

// ---------------------------------------------------------------------------
// Flash-attention (fp32, causal) — unchanged from R1.
// ---------------------------------------------------------------------------
#define LDP 68

__global__ __launch_bounds__(256) void attn_kernel(
    const float* __restrict__ proj, float* __restrict__ out)
{
    extern __shared__ float smf[];
    float* Qs = smf;
    float* Ks = Qs + 64 * LDP;
    float* Vs = Ks + 64 * LDP;
    float* Ps = Vs + 64 * LDP;
    float* mrow = Ps + 64 * LDP;
    float* lrow = mrow + 64;
    float* arow = lrow + 64;

    const int qb = blockIdx.x;
    const int bh = blockIdx.y;
    const int b = bh / HH, h = bh % HH;
    const int tid = threadIdx.x;
    const int tx = tid & 15;
    const int ty = tid >> 4;

    const size_t rowstride = 3 * DD;
    const float* base = proj + (size_t)b * SS * rowstride;
    const int koff = h * HD;
    const int qoff = DD + h * HD;
    const int voff = 2 * DD + h * HD;

    for (int i = tid; i < 64 * 16; i += 256) {
        int r = i >> 4, c4 = (i & 15) * 4;
        *(float4*)(Qs + r * LDP + c4) =
            *(const float4*)(base + (size_t)(qb * 64 + r) * rowstride + qoff + c4);
    }
    if (tid < 64) { mrow[tid] = -1e30f; lrow[tid] = 0.f; }

    float o[4][4];
#pragma unroll
    for (int i = 0; i < 4; i++)
#pragma unroll
        for (int j = 0; j < 4; j++) o[i][j] = 0.f;

    const float scale = 0.125f;

    for (int kb = 0; kb <= qb; ++kb) {
        __syncthreads();
        for (int i = tid; i < 64 * 16; i += 256) {
            int r = i >> 4, c4 = (i & 15) * 4;
            const float* rp = base + (size_t)(kb * 64 + r) * rowstride;
            *(float4*)(Ks + r * LDP + c4) = *(const float4*)(rp + koff + c4);
            *(float4*)(Vs + r * LDP + c4) = *(const float4*)(rp + voff + c4);
        }
        __syncthreads();

        float sacc[4][4];
#pragma unroll
        for (int i = 0; i < 4; i++)
#pragma unroll
            for (int j = 0; j < 4; j++) sacc[i][j] = 0.f;

#pragma unroll 4
        for (int d = 0; d < 64; d += 4) {
            float4 qv[4], kv[4];
#pragma unroll
            for (int i = 0; i < 4; i++) qv[i] = *(float4*)(Qs + (ty * 4 + i) * LDP + d);
#pragma unroll
            for (int j = 0; j < 4; j++) kv[j] = *(float4*)(Ks + (tx * 4 + j) * LDP + d);
#pragma unroll
            for (int i = 0; i < 4; i++)
#pragma unroll
                for (int j = 0; j < 4; j++) {
                    sacc[i][j] += qv[i].x * kv[j].x;
                    sacc[i][j] += qv[i].y * kv[j].y;
                    sacc[i][j] += qv[i].z * kv[j].z;
                    sacc[i][j] += qv[i].w * kv[j].w;
                }
        }

        const int qg0 = qb * 64, kg0 = kb * 64;
#pragma unroll
        for (int i = 0; i < 4; i++) {
            int qi = qg0 + ty * 4 + i;
#pragma unroll
            for (int j = 0; j < 4; j++) {
                int kj = kg0 + tx * 4 + j;
                Ps[(ty * 4 + i) * LDP + tx * 4 + j] =
                    (kj <= qi) ? sacc[i][j] * scale : -1e30f;
            }
        }
        __syncthreads();

        if (tid < 64) {
            const int r = tid;
            float* srow = Ps + r * LDP;
            float mold = mrow[r];
            float mx = mold;
#pragma unroll 8
            for (int j = 0; j < 64; j++) mx = fmaxf(mx, srow[j]);
            float alpha = __expf(mold - mx);
            float sum = 0.f;
#pragma unroll 8
            for (int j = 0; j < 64; j++) {
                float p = __expf(srow[j] - mx);
                srow[j] = p;
                sum += p;
            }
            lrow[r] = lrow[r] * alpha + sum;
            arow[r] = alpha;
            mrow[r] = mx;
        }
        __syncthreads();

#pragma unroll
        for (int i = 0; i < 4; i++) {
            float a = arow[ty * 4 + i];
#pragma unroll
            for (int j = 0; j < 4; j++) o[i][j] *= a;
        }

#pragma unroll 4
        for (int j4 = 0; j4 < 64; j4 += 4) {
            float4 pv[4], vv[4];
#pragma unroll
            for (int i = 0; i < 4; i++) pv[i] = *(float4*)(Ps + (ty * 4 + i) * LDP + j4);
#pragma unroll
            for (int jj = 0; jj < 4; jj++) vv[jj] = *(float4*)(Vs + (j4 + jj) * LDP + tx * 4);
#pragma unroll
            for (int i = 0; i < 4; i++) {
                float p0 = pv[i].x, p1 = pv[i].y, p2 = pv[i].z, p3 = pv[i].w;
                o[i][0] += p0 * vv[0].x + p1 * vv[1].x + p2 * vv[2].x + p3 * vv[3].x;
                o[i][1] += p0 * vv[0].y + p1 * vv[1].y + p2 * vv[2].y + p3 * vv[3].y;
                o[i][2] += p0 * vv[0].z + p1 * vv[1].z + p2 * vv[2].z + p3 * vv[3].z;
                o[i][3] += p0 * vv[0].w + p1 * vv[1].w + p2 * vv[2].w + p3 * vv[3].w;
            }
        }
    }

#pragma unroll
    for (int i = 0; i < 4; i++) {
        float inv = 1.f / lrow[ty * 4 + i];
        float4 ov;
        ov.x = o[i][0] * inv;
        ov.y = o[i][1] * inv;
        ov.z = o[i][2] * inv;
        ov.w = o[i][3] * inv;
        *(float4*)(out + (size_t)(b * SS + qb * 64 + ty * 4 + i) * DD + h * HD + tx * 4) = ov;
    }
}

// ---------------------------------------------------------------------------
extern "C" void kernel_launch(void* const* d_in, const int* in_sizes, int n_in,
                              void* d_out, int out_size)
{
    const float* x     = (const float*)d_in[0];
    const float* W_in  = (const float*)d_in[1];
    const float* b_in  = (const float*)d_in[2];
    const float* W_out = (const float*)d_in[3];
    const float* b_out = (const float*)d_in[4];
    float* out = (float*)d_out;

    float *proj, *attn;
    __nv_bfloat16 *xh, *xl, *w1h, *w1l, *w2h, *w2l, *ah, *al;
    cudaGetSymbolAddress((void**)&proj, g_proj);
    cudaGetSymbolAddress((void**)&attn, g_attn);
    cudaGetSymbolAddress((void**)&xh, g_xh);
    cudaGetSymbolAddress((void**)&xl, g_xl);
    cudaGetSymbolAddress((void**)&w1h, g_w1h);
    cudaGetSymbolAddress((void**)&w1l, g_w1l);
    cudaGetSymbolAddress((void**)&w2h, g_w2h);
    cudaGetSymbolAddress((void**)&w2l, g_w2l);
    cudaGetSymbolAddress((void**)&ah, g_ah);
    cudaGetSymbolAddress((void**)&al, g_al);

    // prep: split x, transpose+split weights
    split_bf16<<<(BS * DD / 4 + 255) / 256, 256>>>(x, xh, xl, BS * DD / 4);
    transpose_split<<<dim3(3 * DD / 32, DD / 32), dim3(32, 8)>>>(W_in, w1h, w1l, DD, 3 * DD);
    transpose_split<<<dim3(DD / 32, DD / 32), dim3(32, 8)>>>(W_out, w2h, w2l, DD, DD);

    // 1) QKV projection on tensor cores (mma.sync)
    gemm_mma<<<dim3(3 * DD / 128, BS / 128), 256>>>(
        xh, xl, w1h, w1l, b_in, proj, BS, 3 * DD, DD);

    // 2) attention (fp32)
    {
        const int smem_bytes = (4 * 64 * LDP + 3 * 64) * (int)sizeof(float);
        cudaFuncSetAttribute(attn_kernel, cudaFuncAttributeMaxDynamicSharedMemorySize, smem_bytes);
        dim3 grid(SS / 64, BB * HH);
        attn_kernel<<<grid, 256, smem_bytes>>>(proj, attn);
    }

    // split attention output for GEMM2
    split_bf16<<<(BS * DD / 4 + 255) / 256, 256>>>(attn, ah, al, BS * DD / 4);

    // 3) output projection on tensor cores (mma.sync)
    gemm_mma<<<dim3(DD / 128, BS / 128), 256>>>(
        ah, al, w2h, w2l, b_out, out, BS, DD, DD);
}

// round 4
// speedup vs baseline: 2.6812x; 2.1198x over previous
#include <cuda_runtime.h>
#include <cuda_bf16.h>
#include <cstdint>

// Problem constants
#define BB   4
#define SS   2048
#define DD   1024
#define HH   16
#define HD   64
#define BS   (BB*SS)        // 8192

__device__ __forceinline__ uint32_t smem_u32(const void* p) {
    uint32_t a;
    asm("{ .reg .u64 t; cvta.to.shared.u64 t, %1; cvt.u32.u64 %0, t; }" : "=r"(a) : "l"(p));
    return a;
}

// ---------------------------------------------------------------------------
// Scratch (device globals)
// ---------------------------------------------------------------------------
__device__ float g_proj[(size_t)BS * 3 * DD];     // [8192, 3072]  k|q|v  (fp32)
__device__ __nv_bfloat16 g_xh[(size_t)BS * DD];
__device__ __nv_bfloat16 g_xl[(size_t)BS * DD];
__device__ __nv_bfloat16 g_w1h[(size_t)(3*DD) * DD]; // W_in^T  [3072,1024]
__device__ __nv_bfloat16 g_w1l[(size_t)(3*DD) * DD];
__device__ __nv_bfloat16 g_w2h[(size_t)DD * DD];     // W_out^T [1024,1024]
__device__ __nv_bfloat16 g_w2l[(size_t)DD * DD];
__device__ __nv_bfloat16 g_ah[(size_t)BS * DD];   // attention out split hi
__device__ __nv_bfloat16 g_al[(size_t)BS * DD];   // attention out split lo

// ---------------------------------------------------------------------------
// Prep: elementwise bf16 2-term split
// ---------------------------------------------------------------------------
__global__ __launch_bounds__(256) void split_bf16(
    const float* __restrict__ src, __nv_bfloat16* __restrict__ hi,
    __nv_bfloat16* __restrict__ lo, int n4)
{
    int i = blockIdx.x * 256 + threadIdx.x;
    if (i >= n4) return;
    float4 v = ((const float4*)src)[i];
    __nv_bfloat162 h0, h1, l0, l1;
    float hx;
    hx = __bfloat162float(__float2bfloat16(v.x)); h0.x = __float2bfloat16(v.x); l0.x = __float2bfloat16(v.x - hx);
    hx = __bfloat162float(__float2bfloat16(v.y)); h0.y = __float2bfloat16(v.y); l0.y = __float2bfloat16(v.y - hx);
    hx = __bfloat162float(__float2bfloat16(v.z)); h1.x = __float2bfloat16(v.z); l1.x = __float2bfloat16(v.z - hx);
    hx = __bfloat162float(__float2bfloat16(v.w)); h1.y = __float2bfloat16(v.w); l1.y = __float2bfloat16(v.w - hx);
    ((__nv_bfloat162*)hi)[i*2+0] = h0; ((__nv_bfloat162*)hi)[i*2+1] = h1;
    ((__nv_bfloat162*)lo)[i*2+0] = l0; ((__nv_bfloat162*)lo)[i*2+1] = l1;
}

// ---------------------------------------------------------------------------
// Prep: transpose + split   W[K,N] -> Th/Tl[N,K]
// ---------------------------------------------------------------------------
__global__ __launch_bounds__(256) void transpose_split(
    const float* __restrict__ W, __nv_bfloat16* __restrict__ th,
    __nv_bfloat16* __restrict__ tl, int K, int N)
{
    __shared__ float tile[32][33];
    int k0 = blockIdx.y * 32, n0 = blockIdx.x * 32;
    int tx = threadIdx.x, ty = threadIdx.y;   // 32 x 8
#pragma unroll
    for (int j = 0; j < 32; j += 8)
        tile[ty + j][tx] = W[(size_t)(k0 + ty + j) * N + n0 + tx];
    __syncthreads();
#pragma unroll
    for (int j = 0; j < 32; j += 8) {
        float v = tile[tx][ty + j];
        __nv_bfloat16 h = __float2bfloat16(v);
        __nv_bfloat16 l = __float2bfloat16(v - __bfloat162float(h));
        size_t o = (size_t)(n0 + ty + j) * K + k0 + tx;
        th[o] = h; tl[o] = l;
    }
}

// ---------------------------------------------------------------------------
// mma.sync helpers
// ---------------------------------------------------------------------------
__device__ __forceinline__ void ldsm_x4(uint32_t& r0, uint32_t& r1, uint32_t& r2, uint32_t& r3,
                                        uint32_t addr) {
    asm volatile("ldmatrix.sync.aligned.m8n8.x4.shared.b16 {%0,%1,%2,%3}, [%4];"
                 : "=r"(r0), "=r"(r1), "=r"(r2), "=r"(r3) : "r"(addr));
}
__device__ __forceinline__ void ldsm_x4_t(uint32_t& r0, uint32_t& r1, uint32_t& r2, uint32_t& r3,
                                          uint32_t addr) {
    asm volatile("ldmatrix.sync.aligned.m8n8.x4.trans.shared.b16 {%0,%1,%2,%3}, [%4];"
                 : "=r"(r0), "=r"(r1), "=r"(r2), "=r"(r3) : "r"(addr));
}
__device__ __forceinline__ void mma_bf16(float* d, const uint32_t* a, uint32_t b0, uint32_t b1) {
    asm volatile(
        "mma.sync.aligned.m16n8k16.row.col.f32.bf16.bf16.f32 "
        "{%0,%1,%2,%3}, {%4,%5,%6,%7}, {%8,%9}, {%0,%1,%2,%3};"
        : "+f"(d[0]), "+f"(d[1]), "+f"(d[2]), "+f"(d[3])
        : "r"(a[0]), "r"(a[1]), "r"(a[2]), "r"(a[3]), "r"(b0), "r"(b1));
}
__device__ __forceinline__ uint32_t pack_hi2(float x, float y) {
    __nv_bfloat162 t = __floats2bfloat162_rn(x, y);
    return *(uint32_t*)&t;
}
__device__ __forceinline__ uint32_t pack_lo2(float x, float y) {
    float hx = __bfloat162float(__float2bfloat16(x));
    float hy = __bfloat162float(__float2bfloat16(y));
    __nv_bfloat162 t = __floats2bfloat162_rn(x - hx, y - hy);
    return *(uint32_t*)&t;
}

// ---------------------------------------------------------------------------
// GEMM on mma.sync (unchanged from R3)
// ---------------------------------------------------------------------------
#define PA 40

__global__ __launch_bounds__(256) void gemm_mma(
    const __nv_bfloat16* __restrict__ Ah, const __nv_bfloat16* __restrict__ Al,
    const __nv_bfloat16* __restrict__ Bh, const __nv_bfloat16* __restrict__ Bl,
    const float* __restrict__ bias, float* __restrict__ C,
    int M, int N, int K)
{
    __shared__ __nv_bfloat16 sm[4 * 128 * PA];
    __nv_bfloat16* sTile[4] = { sm, sm + 128*PA, sm + 2*128*PA, sm + 3*128*PA };

    const int tid  = threadIdx.x;
    const int wid  = tid >> 5;
    const int lane = tid & 31;
    const int wrow = wid & 3;
    const int wcol = wid >> 2;
    const int m0 = blockIdx.y * 128;
    const int n0 = blockIdx.x * 128;

    const uint32_t uS[4] = { smem_u32(sTile[0]), smem_u32(sTile[1]),
                             smem_u32(sTile[2]), smem_u32(sTile[3]) };

    const int a_row = wrow * 32 + (lane & 7) + ((lane >> 3) & 1) * 8;
    const int a_k   = (lane >> 4) * 8;
    const int b_row = wcol * 64 + (lane >> 4) * 8 + (lane & 7);
    const int b_k   = ((lane >> 3) & 1) * 8;

    float acc[2][8][4];
#pragma unroll
    for (int i = 0; i < 2; i++)
#pragma unroll
        for (int j = 0; j < 8; j++)
#pragma unroll
            for (int v = 0; v < 4; v++) acc[i][j][v] = 0.f;

    const __nv_bfloat16* gsrc[4] = {
        Ah + (size_t)m0 * K, Al + (size_t)m0 * K,
        Bh + (size_t)n0 * K, Bl + (size_t)n0 * K };

    const int nchunks = K >> 5;
    for (int kc = 0; kc < nchunks; ++kc) {
        const int k0 = kc << 5;
        __syncthreads();
#pragma unroll
        for (int v = tid; v < 2048; v += 256) {
            int t = v >> 9, idx = v & 511;
            int r = idx >> 2, c = idx & 3;
            uint4 d = *(const uint4*)(gsrc[t] + (size_t)r * K + k0 + c * 8);
            *(uint4*)(sTile[t] + r * PA + c * 8) = d;
        }
        __syncthreads();

#pragma unroll
        for (int pass = 0; pass < 3; pass++) {
            const uint32_t uA = (pass == 2) ? uS[1] : uS[0];
            const uint32_t uB = (pass == 1) ? uS[3] : uS[2];
#pragma unroll
            for (int ks = 0; ks < 2; ks++) {
                uint32_t afr[2][4];
#pragma unroll
                for (int mi = 0; mi < 2; mi++)
                    ldsm_x4(afr[mi][0], afr[mi][1], afr[mi][2], afr[mi][3],
                            uA + 2 * ((a_row + mi * 16) * PA + ks * 16 + a_k));
#pragma unroll
                for (int j = 0; j < 4; j++) {
                    uint32_t r0, r1, r2, r3;
                    ldsm_x4(r0, r1, r2, r3,
                            uB + 2 * ((b_row + j * 16) * PA + ks * 16 + b_k));
#pragma unroll
                    for (int mi = 0; mi < 2; mi++) {
                        mma_bf16(acc[mi][2*j],   afr[mi], r0, r1);
                        mma_bf16(acc[mi][2*j+1], afr[mi], r2, r3);
                    }
                }
            }
        }
    }

    const int row0 = m0 + wrow * 32 + (lane >> 2);
    const int colb = n0 + wcol * 64 + (lane & 3) * 2;
#pragma unroll
    for (int mi = 0; mi < 2; mi++) {
#pragma unroll
        for (int nj = 0; nj < 8; nj++) {
            int c = colb + nj * 8;
            float2 bv = *(const float2*)(bias + c);
            float2 o0 = { acc[mi][nj][0] + bv.x, acc[mi][nj][1] + bv.y };
            float2 o1 = { acc[mi][nj][2] + bv.x, acc[mi][nj][3] + bv.y };
            *(float2*)(C + (size_t)(row0 + mi * 16) * N + c) = o0;
            *(float2*)(C + (size_t)(row0 + mi * 16 + 8) * N + c) = o1;
        }
    }
}

// ---------------------------------------------------------------------------
// Flash-attention on mma.sync, 3-term bf16 split, causal.
// CTA: 128 q-rows x one (b,h). 8 warps, each 16 q-rows.
// Outputs split bf16 (oh/ol) directly for the out-projection GEMM.
// ---------------------------------------------------------------------------
#define PT 72   // smem pitch in bf16 (conflict-free for ldmatrix; 144B rows)

__global__ __launch_bounds__(256) void attn_mma(
    const float* __restrict__ proj,
    __nv_bfloat16* __restrict__ oh, __nv_bfloat16* __restrict__ ol)
{
    extern __shared__ __nv_bfloat16 sb[];
    __nv_bfloat16* Qh = sb;
    __nv_bfloat16* Ql = Qh + 128 * PT;
    __nv_bfloat16* Kh = Ql + 128 * PT;
    __nv_bfloat16* Kl = Kh + 128 * PT;
    __nv_bfloat16* Vh = Kl + 128 * PT;
    __nv_bfloat16* Vl = Vh + 128 * PT;

    const int qb = blockIdx.x;      // q block (128 rows)
    const int bh = blockIdx.y;
    const int b = bh / HH, h = bh % HH;
    const int tid = threadIdx.x, w = tid >> 5, lane = tid & 31;
    const int quad = lane & 3, trow = lane >> 2;

    const uint32_t uQh = smem_u32(Qh), uQl = smem_u32(Ql);
    const uint32_t uKh = smem_u32(Kh), uKl = smem_u32(Kl);
    const uint32_t uVh = smem_u32(Vh), uVl = smem_u32(Vl);

    const size_t rowstride = 3 * DD;
    const float* base = proj + (size_t)b * SS * rowstride;
    const int koff = h * HD, qoff = DD + h * HD, voff = 2 * DD + h * HD;

    // Load Q tile (scale 1/8 folded in — exact in bf16)
#pragma unroll
    for (int i = tid; i < 128 * 16; i += 256) {
        int r = i >> 4, c4 = (i & 15) * 4;
        float4 v = *(const float4*)(base + (size_t)(qb * 128 + r) * rowstride + qoff + c4);
        v.x *= 0.125f; v.y *= 0.125f; v.z *= 0.125f; v.w *= 0.125f;
        float hx = __bfloat162float(__float2bfloat16(v.x));
        float hy = __bfloat162float(__float2bfloat16(v.y));
        float hz = __bfloat162float(__float2bfloat16(v.z));
        float hw = __bfloat162float(__float2bfloat16(v.w));
        *(__nv_bfloat162*)(Qh + r * PT + c4)     = __floats2bfloat162_rn(v.x, v.y);
        *(__nv_bfloat162*)(Qh + r * PT + c4 + 2) = __floats2bfloat162_rn(v.z, v.w);
        *(__nv_bfloat162*)(Ql + r * PT + c4)     = __floats2bfloat162_rn(v.x - hx, v.y - hy);
        *(__nv_bfloat162*)(Ql + r * PT + c4 + 2) = __floats2bfloat162_rn(v.z - hz, v.w - hw);
    }

    float acc_o[8][4];
#pragma unroll
    for (int j = 0; j < 8; j++)
#pragma unroll
        for (int v = 0; v < 4; v++) acc_o[j][v] = 0.f;
    float m0 = -1e30f, m1 = -1e30f, l0 = 0.f, l1 = 0.f;

    for (int kb = 0; kb <= qb; ++kb) {
        __syncthreads();
        // load K, V tiles (128 x 64), split bf16
#pragma unroll
        for (int i = tid; i < 128 * 16; i += 256) {
            int r = i >> 4, c4 = (i & 15) * 4;
            const float* rp = base + (size_t)(kb * 128 + r) * rowstride;
            float4 kv = *(const float4*)(rp + koff + c4);
            float4 vv = *(const float4*)(rp + voff + c4);
            float hx, hy, hz, hw;
            hx = __bfloat162float(__float2bfloat16(kv.x));
            hy = __bfloat162float(__float2bfloat16(kv.y));
            hz = __bfloat162float(__float2bfloat16(kv.z));
            hw = __bfloat162float(__float2bfloat16(kv.w));
            *(__nv_bfloat162*)(Kh + r * PT + c4)     = __floats2bfloat162_rn(kv.x, kv.y);
            *(__nv_bfloat162*)(Kh + r * PT + c4 + 2) = __floats2bfloat162_rn(kv.z, kv.w);
            *(__nv_bfloat162*)(Kl + r * PT + c4)     = __floats2bfloat162_rn(kv.x - hx, kv.y - hy);
            *(__nv_bfloat162*)(Kl + r * PT + c4 + 2) = __floats2bfloat162_rn(kv.z - hz, kv.w - hw);
            hx = __bfloat162float(__float2bfloat16(vv.x));
            hy = __bfloat162float(__float2bfloat16(vv.y));
            hz = __bfloat162float(__float2bfloat16(vv.z));
            hw = __bfloat162float(__float2bfloat16(vv.w));
            *(__nv_bfloat162*)(Vh + r * PT + c4)     = __floats2bfloat162_rn(vv.x, vv.y);
            *(__nv_bfloat162*)(Vh + r * PT + c4 + 2) = __floats2bfloat162_rn(vv.z, vv.w);
            *(__nv_bfloat162*)(Vl + r * PT + c4)     = __floats2bfloat162_rn(vv.x - hx, vv.y - hy);
            *(__nv_bfloat162*)(Vl + r * PT + c4 + 2) = __floats2bfloat162_rn(vv.z - hz, vv.w - hw);
        }
        __syncthreads();

        // ---- S = Q @ K^T (3 split passes) ----
        float s[16][4];
#pragma unroll
        for (int j = 0; j < 16; j++)
#pragma unroll
            for (int v = 0; v < 4; v++) s[j][v] = 0.f;

#pragma unroll
        for (int pass = 0; pass < 3; pass++) {
            const uint32_t uA = (pass == 2) ? uQl : uQh;
            const uint32_t uB = (pass == 1) ? uKl : uKh;
#pragma unroll
            for (int kc = 0; kc < 4; kc++) {
                uint32_t a[4];
                ldsm_x4(a[0], a[1], a[2], a[3],
                        uA + 2 * ((w * 16 + (lane & 15)) * PT + kc * 16 + (lane >> 4) * 8));
#pragma unroll
                for (int ntp = 0; ntp < 8; ntp++) {
                    uint32_t b0, b1, b2, b3;
                    ldsm_x4(b0, b1, b2, b3,
                            uB + 2 * ((ntp * 16 + (lane & 15)) * PT + kc * 16 + (lane >> 4) * 8));
                    mma_bf16(s[2*ntp],   a, b0, b2);
                    mma_bf16(s[2*ntp+1], a, b1, b3);
                }
            }
        }

        // causal mask (diagonal block only)
        if (kb == qb) {
            const int rl0 = w * 16 + trow;
#pragma unroll
            for (int nt = 0; nt < 16; nt++) {
                int c0 = nt * 8 + 2 * quad;
                if (c0 > rl0)     s[nt][0] = -1e30f;
                if (c0 + 1 > rl0) s[nt][1] = -1e30f;
                if (c0 > rl0 + 8)     s[nt][2] = -1e30f;
                if (c0 + 1 > rl0 + 8) s[nt][3] = -1e30f;
            }
        }

        // ---- online softmax ----
        float mx0 = -1e30f, mx1 = -1e30f;
#pragma unroll
        for (int nt = 0; nt < 16; nt++) {
            mx0 = fmaxf(mx0, fmaxf(s[nt][0], s[nt][1]));
            mx1 = fmaxf(mx1, fmaxf(s[nt][2], s[nt][3]));
        }
        mx0 = fmaxf(mx0, __shfl_xor_sync(0xffffffffu, mx0, 1));
        mx0 = fmaxf(mx0, __shfl_xor_sync(0xffffffffu, mx0, 2));
        mx1 = fmaxf(mx1, __shfl_xor_sync(0xffffffffu, mx1, 1));
        mx1 = fmaxf(mx1, __shfl_xor_sync(0xffffffffu, mx1, 2));
        float m0n = fmaxf(m0, mx0), m1n = fmaxf(m1, mx1);
        float al0 = __expf(m0 - m0n), al1 = __expf(m1 - m1n);
        m0 = m0n; m1 = m1n;

        float sum0 = 0.f, sum1 = 0.f;
#pragma unroll
        for (int nt = 0; nt < 16; nt++) {
            s[nt][0] = __expf(s[nt][0] - m0); sum0 += s[nt][0];
            s[nt][1] = __expf(s[nt][1] - m0); sum0 += s[nt][1];
            s[nt][2] = __expf(s[nt][2] - m1); sum1 += s[nt][2];
            s[nt][3] = __expf(s[nt][3] - m1); sum1 += s[nt][3];
        }
        sum0 += __shfl_xor_sync(0xffffffffu, sum0, 1);
        sum0 += __shfl_xor_sync(0xffffffffu, sum0, 2);
        sum1 += __shfl_xor_sync(0xffffffffu, sum1, 1);
        sum1 += __shfl_xor_sync(0xffffffffu, sum1, 2);
        l0 = l0 * al0 + sum0;
        l1 = l1 * al1 + sum1;

#pragma unroll
        for (int j = 0; j < 8; j++) {
            acc_o[j][0] *= al0; acc_o[j][1] *= al0;
            acc_o[j][2] *= al1; acc_o[j][3] *= al1;
        }

        // ---- O += P @ V (3 split passes, fused per k-chunk) ----
#pragma unroll
        for (int kc = 0; kc < 8; kc++) {
            uint32_t pha[4], pla[4];
            pha[0] = pack_hi2(s[2*kc][0],   s[2*kc][1]);
            pha[1] = pack_hi2(s[2*kc][2],   s[2*kc][3]);
            pha[2] = pack_hi2(s[2*kc+1][0], s[2*kc+1][1]);
            pha[3] = pack_hi2(s[2*kc+1][2], s[2*kc+1][3]);
            pla[0] = pack_lo2(s[2*kc][0],   s[2*kc][1]);
            pla[1] = pack_lo2(s[2*kc][2],   s[2*kc][3]);
            pla[2] = pack_lo2(s[2*kc+1][0], s[2*kc+1][1]);
            pla[3] = pack_lo2(s[2*kc+1][2], s[2*kc+1][3]);
#pragma unroll
            for (int ht = 0; ht < 4; ht++) {
                uint32_t vh0, vh1, vh2, vh3, vl0, vl1, vl2, vl3;
                uint32_t off = 2 * ((kc * 16 + (lane & 15)) * PT + ht * 16 + (lane >> 4) * 8);
                ldsm_x4_t(vh0, vh1, vh2, vh3, uVh + off);
                ldsm_x4_t(vl0, vl1, vl2, vl3, uVl + off);
                mma_bf16(acc_o[2*ht],   pha, vh0, vh1);
                mma_bf16(acc_o[2*ht+1], pha, vh2, vh3);
                mma_bf16(acc_o[2*ht],   pha, vl0, vl1);
                mma_bf16(acc_o[2*ht+1], pha, vl2, vl3);
                mma_bf16(acc_o[2*ht],   pla, vh0, vh1);
                mma_bf16(acc_o[2*ht+1], pla, vh2, vh3);
            }
        }
    }

    // normalize and write split-bf16 output
    const float inv0 = 1.f / l0, inv1 = 1.f / l1;
    const size_t grow0 = (size_t)(b * SS + qb * 128 + w * 16 + trow);
    const size_t grow1 = grow0 + 8;
#pragma unroll
    for (int j = 0; j < 8; j++) {
        int c = h * HD + j * 8 + 2 * quad;
        float o00 = acc_o[j][0] * inv0, o01 = acc_o[j][1] * inv0;
        float o10 = acc_o[j][2] * inv1, o11 = acc_o[j][3] * inv1;
        *(uint32_t*)(oh + grow0 * DD + c) = pack_hi2(o00, o01);
        *(uint32_t*)(ol + grow0 * DD + c) = pack_lo2(o00, o01);
        *(uint32_t*)(oh + grow1 * DD + c) = pack_hi2(o10, o11);
        *(uint32_t*)(ol + grow1 * DD + c) = pack_lo2(o10, o11);
    }
}

// ---------------------------------------------------------------------------
extern "C" void kernel_launch(void* const* d_in, const int* in_sizes, int n_in,
                              void* d_out, int out_size)
{
    const float* x     = (const float*)d_in[0];
    const float* W_in  = (const float*)d_in[1];
    const float* b_in  = (const float*)d_in[2];
    const float* W_out = (const float*)d_in[3];
    const float* b_out = (const float*)d_in[4];
    float* out = (float*)d_out;

    float *proj;
    __nv_bfloat16 *xh, *xl, *w1h, *w1l, *w2h, *w2l, *ah, *al;
    cudaGetSymbolAddress((void**)&proj, g_proj);
    cudaGetSymbolAddress((void**)&xh, g_xh);
    cudaGetSymbolAddress((void**)&xl, g_xl);
    cudaGetSymbolAddress((void**)&w1h, g_w1h);
    cudaGetSymbolAddress((void**)&w1l, g_w1l);
    cudaGetSymbolAddress((void**)&w2h, g_w2h);
    cudaGetSymbolAddress((void**)&w2l, g_w2l);
    cudaGetSymbolAddress((void**)&ah, g_ah);
    cudaGetSymbolAddress((void**)&al, g_al);

    // prep
    split_bf16<<<(BS * DD / 4 + 255) / 256, 256>>>(x, xh, xl, BS * DD / 4);
    transpose_split<<<dim3(3 * DD / 32, DD / 32), dim3(32, 8)>>>(W_in, w1h, w1l, DD, 3 * DD);
    transpose_split<<<dim3(DD / 32, DD / 32), dim3(32, 8)>>>(W_out, w2h, w2l, DD, DD);

    // 1) QKV projection
    gemm_mma<<<dim3(3 * DD / 128, BS / 128), 256>>>(
        xh, xl, w1h, w1l, b_in, proj, BS, 3 * DD, DD);

    // 2) attention on tensor cores; writes split bf16 directly
    {
        const int smem_bytes = 6 * 128 * PT * (int)sizeof(__nv_bfloat16);  // 110592
        cudaFuncSetAttribute(attn_mma, cudaFuncAttributeMaxDynamicSharedMemorySize, smem_bytes);
        dim3 grid(SS / 128, BB * HH);
        attn_mma<<<grid, 256, smem_bytes>>>(proj, ah, al);
    }

    // 3) output projection
    gemm_mma<<<dim3(DD / 128, BS / 128), 256>>>(
        ah, al, w2h, w2l, b_out, out, BS, DD, DD);
}

// round 5
// speedup vs baseline: 3.1489x; 1.1744x over previous
#include <cuda_runtime.h>
#include <cuda_bf16.h>
#include <cstdint>

// Problem constants
#define BB   4
#define SS   2048
#define DD   1024
#define HH   16
#define HD   64
#define BS   (BB*SS)        // 8192

__device__ __forceinline__ uint32_t smem_u32(const void* p) {
    uint32_t a;
    asm("{ .reg .u64 t; cvta.to.shared.u64 t, %1; cvt.u32.u64 %0, t; }" : "=r"(a) : "l"(p));
    return a;
}
__device__ __forceinline__ void cp16(uint32_t dst, const void* src) {
    asm volatile("cp.async.cg.shared.global [%0], [%1], 16;" :: "r"(dst), "l"(src));
}
#define CP_COMMIT() asm volatile("cp.async.commit_group;" ::: "memory")
#define CP_WAIT0()  asm volatile("cp.async.wait_group 0;" ::: "memory")

// ---------------------------------------------------------------------------
// Scratch (device globals)
// ---------------------------------------------------------------------------
__device__ __nv_bfloat16 g_xh[(size_t)BS * DD];
__device__ __nv_bfloat16 g_xl[(size_t)BS * DD];
__device__ __nv_bfloat16 g_w1h[(size_t)(3*DD) * DD]; // W_in^T  [3072,1024]
__device__ __nv_bfloat16 g_w1l[(size_t)(3*DD) * DD];
__device__ __nv_bfloat16 g_w2h[(size_t)DD * DD];     // W_out^T [1024,1024]
__device__ __nv_bfloat16 g_w2l[(size_t)DD * DD];
__device__ __nv_bfloat16 g_ph[(size_t)BS * 3 * DD];  // proj split hi (k|q|v)
__device__ __nv_bfloat16 g_pl[(size_t)BS * 3 * DD];  // proj split lo
__device__ __nv_bfloat16 g_ah[(size_t)BS * DD];      // attention out split hi
__device__ __nv_bfloat16 g_al[(size_t)BS * DD];      // attention out split lo

// ---------------------------------------------------------------------------
// Prep kernels
// ---------------------------------------------------------------------------
__global__ __launch_bounds__(256) void split_bf16(
    const float* __restrict__ src, __nv_bfloat16* __restrict__ hi,
    __nv_bfloat16* __restrict__ lo, int n4)
{
    int i = blockIdx.x * 256 + threadIdx.x;
    if (i >= n4) return;
    float4 v = ((const float4*)src)[i];
    __nv_bfloat162 h0, h1, l0, l1;
    float hx;
    hx = __bfloat162float(__float2bfloat16(v.x)); h0.x = __float2bfloat16(v.x); l0.x = __float2bfloat16(v.x - hx);
    hx = __bfloat162float(__float2bfloat16(v.y)); h0.y = __float2bfloat16(v.y); l0.y = __float2bfloat16(v.y - hx);
    hx = __bfloat162float(__float2bfloat16(v.z)); h1.x = __float2bfloat16(v.z); l1.x = __float2bfloat16(v.z - hx);
    hx = __bfloat162float(__float2bfloat16(v.w)); h1.y = __float2bfloat16(v.w); l1.y = __float2bfloat16(v.w - hx);
    ((__nv_bfloat162*)hi)[i*2+0] = h0; ((__nv_bfloat162*)hi)[i*2+1] = h1;
    ((__nv_bfloat162*)lo)[i*2+0] = l0; ((__nv_bfloat162*)lo)[i*2+1] = l1;
}

__global__ __launch_bounds__(256) void transpose_split(
    const float* __restrict__ W, __nv_bfloat16* __restrict__ th,
    __nv_bfloat16* __restrict__ tl, int K, int N)
{
    __shared__ float tile[32][33];
    int k0 = blockIdx.y * 32, n0 = blockIdx.x * 32;
    int tx = threadIdx.x, ty = threadIdx.y;   // 32 x 8
#pragma unroll
    for (int j = 0; j < 32; j += 8)
        tile[ty + j][tx] = W[(size_t)(k0 + ty + j) * N + n0 + tx];
    __syncthreads();
#pragma unroll
    for (int j = 0; j < 32; j += 8) {
        float v = tile[tx][ty + j];
        __nv_bfloat16 h = __float2bfloat16(v);
        __nv_bfloat16 l = __float2bfloat16(v - __bfloat162float(h));
        size_t o = (size_t)(n0 + ty + j) * K + k0 + tx;
        th[o] = h; tl[o] = l;
    }
}

// ---------------------------------------------------------------------------
// mma.sync helpers
// ---------------------------------------------------------------------------
__device__ __forceinline__ void ldsm_x4(uint32_t& r0, uint32_t& r1, uint32_t& r2, uint32_t& r3,
                                        uint32_t addr) {
    asm volatile("ldmatrix.sync.aligned.m8n8.x4.shared.b16 {%0,%1,%2,%3}, [%4];"
                 : "=r"(r0), "=r"(r1), "=r"(r2), "=r"(r3) : "r"(addr));
}
__device__ __forceinline__ void ldsm_x4_t(uint32_t& r0, uint32_t& r1, uint32_t& r2, uint32_t& r3,
                                          uint32_t addr) {
    asm volatile("ldmatrix.sync.aligned.m8n8.x4.trans.shared.b16 {%0,%1,%2,%3}, [%4];"
                 : "=r"(r0), "=r"(r1), "=r"(r2), "=r"(r3) : "r"(addr));
}
__device__ __forceinline__ void mma_bf16(float* d, const uint32_t* a, uint32_t b0, uint32_t b1) {
    asm volatile(
        "mma.sync.aligned.m16n8k16.row.col.f32.bf16.bf16.f32 "
        "{%0,%1,%2,%3}, {%4,%5,%6,%7}, {%8,%9}, {%0,%1,%2,%3};"
        : "+f"(d[0]), "+f"(d[1]), "+f"(d[2]), "+f"(d[3])
        : "r"(a[0]), "r"(a[1]), "r"(a[2]), "r"(a[3]), "r"(b0), "r"(b1));
}
__device__ __forceinline__ uint32_t pack_hi2(float x, float y) {
    __nv_bfloat162 t = __floats2bfloat162_rn(x, y);
    return *(uint32_t*)&t;
}
__device__ __forceinline__ uint32_t pack_lo2(float x, float y) {
    float hx = __bfloat162float(__float2bfloat16(x));
    float hy = __bfloat162float(__float2bfloat16(y));
    __nv_bfloat162 t = __floats2bfloat162_rn(x - hx, y - hy);
    return *(uint32_t*)&t;
}

// ---------------------------------------------------------------------------
// GEMM on mma.sync, 3-term split, cp.async 2-stage double buffer.
// C = A @ B^T + bias. Epilogue: fp32 (C) or split bf16 (Ch/Cl) if Ch != null.
// ---------------------------------------------------------------------------
#define PA 40
#define STG (4 * 128 * PA)   // bf16 elems per stage (20480)

__global__ __launch_bounds__(256) void gemm_mma(
    const __nv_bfloat16* __restrict__ Ah, const __nv_bfloat16* __restrict__ Al,
    const __nv_bfloat16* __restrict__ Bh, const __nv_bfloat16* __restrict__ Bl,
    const float* __restrict__ bias,
    float* __restrict__ C, __nv_bfloat16* __restrict__ Ch, __nv_bfloat16* __restrict__ Cl,
    int M, int N, int K)
{
    extern __shared__ __nv_bfloat16 sg[];   // 2 * STG
    const uint32_t uBase = smem_u32(sg);

    const int tid  = threadIdx.x;
    const int wid  = tid >> 5;
    const int lane = tid & 31;
    const int wrow = wid & 3;
    const int wcol = wid >> 2;
    const int m0 = blockIdx.y * 128;
    const int n0 = blockIdx.x * 128;

    const int a_row = wrow * 32 + (lane & 7) + ((lane >> 3) & 1) * 8;
    const int a_k   = (lane >> 4) * 8;
    const int b_row = wcol * 64 + (lane >> 4) * 8 + (lane & 7);
    const int b_k   = ((lane >> 3) & 1) * 8;

    const __nv_bfloat16* gsrc[4] = {
        Ah + (size_t)m0 * K, Al + (size_t)m0 * K,
        Bh + (size_t)n0 * K, Bl + (size_t)n0 * K };

    // loader: 4 tiles of 128 rows x 32 bf16 -> stage buf
    auto load_stage = [&](int kc, int buf) {
        const int k0 = kc << 5;
        const uint32_t sb = uBase + buf * (STG * 2);
#pragma unroll
        for (int v = tid; v < 2048; v += 256) {
            int t = v >> 9, idx = v & 511;
            int r = idx >> 2, c = idx & 3;
            cp16(sb + (t * (128 * PA) + r * PA + c * 8) * 2,
                 gsrc[t] + (size_t)r * K + k0 + c * 8);
        }
    };

    float acc[2][8][4];
#pragma unroll
    for (int i = 0; i < 2; i++)
#pragma unroll
        for (int j = 0; j < 8; j++)
#pragma unroll
            for (int v = 0; v < 4; v++) acc[i][j][v] = 0.f;

    const int nchunks = K >> 5;
    load_stage(0, 0);
    CP_COMMIT();

    for (int kc = 0; kc < nchunks; ++kc) {
        const int buf = kc & 1;
        CP_WAIT0();
        __syncthreads();
        if (kc + 1 < nchunks) {
            load_stage(kc + 1, buf ^ 1);
            CP_COMMIT();
        }
        const uint32_t s0 = uBase + buf * (STG * 2);
        const uint32_t tAh = s0;
        const uint32_t tAl = s0 + (128 * PA) * 2;
        const uint32_t tBh = s0 + 2 * (128 * PA) * 2;
        const uint32_t tBl = s0 + 3 * (128 * PA) * 2;

#pragma unroll
        for (int pass = 0; pass < 3; pass++) {
            const uint32_t uA = (pass == 2) ? tAl : tAh;
            const uint32_t uB = (pass == 1) ? tBl : tBh;
#pragma unroll
            for (int ks = 0; ks < 2; ks++) {
                uint32_t afr[2][4];
#pragma unroll
                for (int mi = 0; mi < 2; mi++)
                    ldsm_x4(afr[mi][0], afr[mi][1], afr[mi][2], afr[mi][3],
                            uA + 2 * ((a_row + mi * 16) * PA + ks * 16 + a_k));
#pragma unroll
                for (int j = 0; j < 4; j++) {
                    uint32_t r0, r1, r2, r3;
                    ldsm_x4(r0, r1, r2, r3,
                            uB + 2 * ((b_row + j * 16) * PA + ks * 16 + b_k));
#pragma unroll
                    for (int mi = 0; mi < 2; mi++) {
                        mma_bf16(acc[mi][2*j],   afr[mi], r0, r1);
                        mma_bf16(acc[mi][2*j+1], afr[mi], r2, r3);
                    }
                }
            }
        }
        __syncthreads();
    }

    const int row0 = m0 + wrow * 32 + (lane >> 2);
    const int colb = n0 + wcol * 64 + (lane & 3) * 2;
#pragma unroll
    for (int mi = 0; mi < 2; mi++) {
#pragma unroll
        for (int nj = 0; nj < 8; nj++) {
            int c = colb + nj * 8;
            float2 bv = *(const float2*)(bias + c);
            float o00 = acc[mi][nj][0] + bv.x, o01 = acc[mi][nj][1] + bv.y;
            float o10 = acc[mi][nj][2] + bv.x, o11 = acc[mi][nj][3] + bv.y;
            size_t r0o = (size_t)(row0 + mi * 16) * N + c;
            size_t r1o = (size_t)(row0 + mi * 16 + 8) * N + c;
            if (Ch) {
                *(uint32_t*)(Ch + r0o) = pack_hi2(o00, o01);
                *(uint32_t*)(Cl + r0o) = pack_lo2(o00, o01);
                *(uint32_t*)(Ch + r1o) = pack_hi2(o10, o11);
                *(uint32_t*)(Cl + r1o) = pack_lo2(o10, o11);
            } else {
                *(float2*)(C + r0o) = make_float2(o00, o01);
                *(float2*)(C + r1o) = make_float2(o10, o11);
            }
        }
    }
}

// ---------------------------------------------------------------------------
// Flash-attention on mma.sync. Reads split-bf16 proj directly (pure copies),
// K/V double-buffered with cp.async. Scale 1/8 applied to S in fp32.
// ---------------------------------------------------------------------------
#define PT 72
#define AT (128 * PT)      // one tile in bf16 elems (9216)
// smem layout (bf16 elems): Qh @0, Ql @AT, stage s tile t @ 2*AT + s*4*AT + t*AT
#define A_SMEM ((2 + 8) * AT * 2)   // 184320 B

__global__ __launch_bounds__(256) void attn_mma(
    const __nv_bfloat16* __restrict__ ph, const __nv_bfloat16* __restrict__ pl,
    __nv_bfloat16* __restrict__ oh, __nv_bfloat16* __restrict__ ol)
{
    extern __shared__ __nv_bfloat16 sb[];
    const uint32_t uBase = smem_u32(sb);
    const uint32_t uQh = uBase, uQl = uBase + AT * 2;

    const int qb = blockIdx.x;
    const int bh = blockIdx.y;
    const int b = bh / HH, h = bh % HH;
    const int tid = threadIdx.x, w = tid >> 5, lane = tid & 31;
    const int quad = lane & 3, trow = lane >> 2;

    const size_t rowstride = 3 * DD;
    const size_t rbase = (size_t)b * SS * rowstride;
    const int koff = h * HD, qoff = DD + h * HD, voff = 2 * DD + h * HD;

    // Q copy (hi+lo): 2 tiles x 128 rows x 8 uint4
#pragma unroll
    for (int i = tid; i < 2048; i += 256) {
        int t = i >> 10, idx = i & 1023;
        int r = idx >> 3, c = idx & 7;
        const __nv_bfloat16* src = (t ? pl : ph) + rbase + (size_t)(qb * 128 + r) * rowstride + qoff + c * 8;
        cp16(uBase + (t * AT + r * PT + c * 8) * 2, src);
    }

    // KV loader into stage buf
    auto load_kv = [&](int kb, int buf) {
        const uint32_t sbs = uBase + (2 * AT + buf * 4 * AT) * 2;
#pragma unroll
        for (int i = tid; i < 4096; i += 256) {
            int t = i >> 10, idx = i & 1023;
            int r = idx >> 3, c = idx & 7;
            const __nv_bfloat16* base = (t & 1) ? pl : ph;
            int off = (t >= 2) ? voff : koff;
            cp16(sbs + (t * AT + r * PT + c * 8) * 2,
                 base + rbase + (size_t)(kb * 128 + r) * rowstride + off + c * 8);
        }
    };

    load_kv(0, 0);
    CP_COMMIT();

    float acc_o[8][4];
#pragma unroll
    for (int j = 0; j < 8; j++)
#pragma unroll
        for (int v = 0; v < 4; v++) acc_o[j][v] = 0.f;
    float m0 = -1e30f, m1 = -1e30f, l0 = 0.f, l1 = 0.f;

    for (int kb = 0; kb <= qb; ++kb) {
        const int buf = kb & 1;
        CP_WAIT0();
        __syncthreads();
        if (kb < qb) {
            load_kv(kb + 1, buf ^ 1);
            CP_COMMIT();
        }
        const uint32_t s0 = uBase + (2 * AT + buf * 4 * AT) * 2;
        const uint32_t uKh = s0, uKl = s0 + AT * 2;
        const uint32_t uVh = s0 + 2 * AT * 2, uVl = s0 + 3 * AT * 2;

        // ---- S = Q @ K^T (3 split passes) ----
        float s[16][4];
#pragma unroll
        for (int j = 0; j < 16; j++)
#pragma unroll
            for (int v = 0; v < 4; v++) s[j][v] = 0.f;

#pragma unroll
        for (int pass = 0; pass < 3; pass++) {
            const uint32_t uA = (pass == 2) ? uQl : uQh;
            const uint32_t uB = (pass == 1) ? uKl : uKh;
#pragma unroll
            for (int kc = 0; kc < 4; kc++) {
                uint32_t a[4];
                ldsm_x4(a[0], a[1], a[2], a[3],
                        uA + 2 * ((w * 16 + (lane & 15)) * PT + kc * 16 + (lane >> 4) * 8));
#pragma unroll
                for (int ntp = 0; ntp < 8; ntp++) {
                    uint32_t b0, b1, b2, b3;
                    ldsm_x4(b0, b1, b2, b3,
                            uB + 2 * ((ntp * 16 + (lane & 15)) * PT + kc * 16 + (lane >> 4) * 8));
                    mma_bf16(s[2*ntp],   a, b0, b2);
                    mma_bf16(s[2*ntp+1], a, b1, b3);
                }
            }
        }

        // scale 1/8 (fp32, exact semantics of reference up to split error)
#pragma unroll
        for (int nt = 0; nt < 16; nt++) {
            s[nt][0] *= 0.125f; s[nt][1] *= 0.125f;
            s[nt][2] *= 0.125f; s[nt][3] *= 0.125f;
        }

        // causal mask (diagonal block only)
        if (kb == qb) {
            const int rl0 = w * 16 + trow;
#pragma unroll
            for (int nt = 0; nt < 16; nt++) {
                int c0 = nt * 8 + 2 * quad;
                if (c0 > rl0)     s[nt][0] = -1e30f;
                if (c0 + 1 > rl0) s[nt][1] = -1e30f;
                if (c0 > rl0 + 8)     s[nt][2] = -1e30f;
                if (c0 + 1 > rl0 + 8) s[nt][3] = -1e30f;
            }
        }

        // ---- online softmax ----
        float mx0 = -1e30f, mx1 = -1e30f;
#pragma unroll
        for (int nt = 0; nt < 16; nt++) {
            mx0 = fmaxf(mx0, fmaxf(s[nt][0], s[nt][1]));
            mx1 = fmaxf(mx1, fmaxf(s[nt][2], s[nt][3]));
        }
        mx0 = fmaxf(mx0, __shfl_xor_sync(0xffffffffu, mx0, 1));
        mx0 = fmaxf(mx0, __shfl_xor_sync(0xffffffffu, mx0, 2));
        mx1 = fmaxf(mx1, __shfl_xor_sync(0xffffffffu, mx1, 1));
        mx1 = fmaxf(mx1, __shfl_xor_sync(0xffffffffu, mx1, 2));
        float m0n = fmaxf(m0, mx0), m1n = fmaxf(m1, mx1);
        float al0 = __expf(m0 - m0n), al1 = __expf(m1 - m1n);
        m0 = m0n; m1 = m1n;

        float sum0 = 0.f, sum1 = 0.f;
#pragma unroll
        for (int nt = 0; nt < 16; nt++) {
            s[nt][0] = __expf(s[nt][0] - m0); sum0 += s[nt][0];
            s[nt][1] = __expf(s[nt][1] - m0); sum0 += s[nt][1];
            s[nt][2] = __expf(s[nt][2] - m1); sum1 += s[nt][2];
            s[nt][3] = __expf(s[nt][3] - m1); sum1 += s[nt][3];
        }
        sum0 += __shfl_xor_sync(0xffffffffu, sum0, 1);
        sum0 += __shfl_xor_sync(0xffffffffu, sum0, 2);
        sum1 += __shfl_xor_sync(0xffffffffu, sum1, 1);
        sum1 += __shfl_xor_sync(0xffffffffu, sum1, 2);
        l0 = l0 * al0 + sum0;
        l1 = l1 * al1 + sum1;

#pragma unroll
        for (int j = 0; j < 8; j++) {
            acc_o[j][0] *= al0; acc_o[j][1] *= al0;
            acc_o[j][2] *= al1; acc_o[j][3] *= al1;
        }

        // ---- O += P @ V (split P and V) ----
#pragma unroll
        for (int kc = 0; kc < 8; kc++) {
            uint32_t pha[4], pla[4];
            pha[0] = pack_hi2(s[2*kc][0],   s[2*kc][1]);
            pha[1] = pack_hi2(s[2*kc][2],   s[2*kc][3]);
            pha[2] = pack_hi2(s[2*kc+1][0], s[2*kc+1][1]);
            pha[3] = pack_hi2(s[2*kc+1][2], s[2*kc+1][3]);
            pla[0] = pack_lo2(s[2*kc][0],   s[2*kc][1]);
            pla[1] = pack_lo2(s[2*kc][2],   s[2*kc][3]);
            pla[2] = pack_lo2(s[2*kc+1][0], s[2*kc+1][1]);
            pla[3] = pack_lo2(s[2*kc+1][2], s[2*kc+1][3]);
#pragma unroll
            for (int ht = 0; ht < 4; ht++) {
                uint32_t vh0, vh1, vh2, vh3, vl0, vl1, vl2, vl3;
                uint32_t off = 2 * ((kc * 16 + (lane & 15)) * PT + ht * 16 + (lane >> 4) * 8);
                ldsm_x4_t(vh0, vh1, vh2, vh3, uVh + off);
                ldsm_x4_t(vl0, vl1, vl2, vl3, uVl + off);
                mma_bf16(acc_o[2*ht],   pha, vh0, vh1);
                mma_bf16(acc_o[2*ht+1], pha, vh2, vh3);
                mma_bf16(acc_o[2*ht],   pha, vl0, vl1);
                mma_bf16(acc_o[2*ht+1], pha, vl2, vl3);
                mma_bf16(acc_o[2*ht],   pla, vh0, vh1);
                mma_bf16(acc_o[2*ht+1], pla, vh2, vh3);
            }
        }
        __syncthreads();
    }

    // normalize and write split-bf16 output
    const float inv0 = 1.f / l0, inv1 = 1.f / l1;
    const size_t grow0 = (size_t)(b * SS + qb * 128 + w * 16 + trow);
    const size_t grow1 = grow0 + 8;
#pragma unroll
    for (int j = 0; j < 8; j++) {
        int c = h * HD + j * 8 + 2 * quad;
        float o00 = acc_o[j][0] * inv0, o01 = acc_o[j][1] * inv0;
        float o10 = acc_o[j][2] * inv1, o11 = acc_o[j][3] * inv1;
        *(uint32_t*)(oh + grow0 * DD + c) = pack_hi2(o00, o01);
        *(uint32_t*)(ol + grow0 * DD + c) = pack_lo2(o00, o01);
        *(uint32_t*)(oh + grow1 * DD + c) = pack_hi2(o10, o11);
        *(uint32_t*)(ol + grow1 * DD + c) = pack_lo2(o10, o11);
    }
}

// ---------------------------------------------------------------------------
extern "C" void kernel_launch(void* const* d_in, const int* in_sizes, int n_in,
                              void* d_out, int out_size)
{
    const float* x     = (const float*)d_in[0];
    const float* W_in  = (const float*)d_in[1];
    const float* b_in  = (const float*)d_in[2];
    const float* W_out = (const float*)d_in[3];
    const float* b_out = (const float*)d_in[4];
    float* out = (float*)d_out;

    __nv_bfloat16 *xh, *xl, *w1h, *w1l, *w2h, *w2l, *ph, *pl, *ah, *al;
    cudaGetSymbolAddress((void**)&xh, g_xh);
    cudaGetSymbolAddress((void**)&xl, g_xl);
    cudaGetSymbolAddress((void**)&w1h, g_w1h);
    cudaGetSymbolAddress((void**)&w1l, g_w1l);
    cudaGetSymbolAddress((void**)&w2h, g_w2h);
    cudaGetSymbolAddress((void**)&w2l, g_w2l);
    cudaGetSymbolAddress((void**)&ph, g_ph);
    cudaGetSymbolAddress((void**)&pl, g_pl);
    cudaGetSymbolAddress((void**)&ah, g_ah);
    cudaGetSymbolAddress((void**)&al, g_al);

    const int gemm_smem = 2 * STG * (int)sizeof(__nv_bfloat16);   // 81920
    cudaFuncSetAttribute(gemm_mma, cudaFuncAttributeMaxDynamicSharedMemorySize, gemm_smem);
    cudaFuncSetAttribute(attn_mma, cudaFuncAttributeMaxDynamicSharedMemorySize, A_SMEM);

    // prep
    split_bf16<<<(BS * DD / 4 + 255) / 256, 256>>>(x, xh, xl, BS * DD / 4);
    transpose_split<<<dim3(3 * DD / 32, DD / 32), dim3(32, 8)>>>(W_in, w1h, w1l, DD, 3 * DD);
    transpose_split<<<dim3(DD / 32, DD / 32), dim3(32, 8)>>>(W_out, w2h, w2l, DD, DD);

    // 1) QKV projection -> split bf16 proj
    gemm_mma<<<dim3(3 * DD / 128, BS / 128), 256, gemm_smem>>>(
        xh, xl, w1h, w1l, b_in, nullptr, ph, pl, BS, 3 * DD, DD);

    // 2) attention
    {
        dim3 grid(SS / 128, BB * HH);
        attn_mma<<<grid, 256, A_SMEM>>>(ph, pl, ah, al);
    }

    // 3) output projection -> fp32 out
    gemm_mma<<<dim3(DD / 128, BS / 128), 256, gemm_smem>>>(
        ah, al, w2h, w2l, b_out, out, nullptr, nullptr, BS, DD, DD);
}